// round 17
// baseline (speedup 1.0000x reference)
#include <cuda_runtime.h>
#include <cuda_bf16.h>
#include <math.h>

#define NN_MAX 50000
#define EE_MAX 600000
#define DD 128
#define HH 4
#define CC 32
#define NEG_SLOPE 0.2f
#define LN_EPS 1e-5f
#define NB_MAX 256
#define TILE_R 32

// ---------------- device scratch ----------------
static __device__ float g_h[NN_MAX * DD];
static __device__ float g_asrc[NN_MAX * HH];
static __device__ float g_adst[NN_MAX * HH];
static __device__ int   g_deg[NN_MAX];
static __device__ int   g_rowoff[NN_MAX];
static __device__ int   g_cursor[NN_MAX];
static __device__ int   g_srclist[EE_MAX];
static __device__ int   g_bsum[NB_MAX];
static __device__ int   g_is64;

// ---------------- f32x2 helpers ----------------
__device__ __forceinline__ unsigned long long pk2(float lo, float hi) {
    unsigned long long r;
    asm("mov.b64 %0, {%1, %2};" : "=l"(r) : "f"(lo), "f"(hi));
    return r;
}
__device__ __forceinline__ unsigned long long fma2(unsigned long long a,
                                                   unsigned long long b,
                                                   unsigned long long c) {
    unsigned long long d;
    asm("fma.rn.f32x2 %0, %1, %2, %3;" : "=l"(d) : "l"(a), "l"(b), "l"(c));
    return d;
}
__device__ __forceinline__ float2 upk2(unsigned long long v) {
    float lo, hi;
    asm("mov.b64 {%0, %1}, %2;" : "=f"(lo), "=f"(hi) : "l"(v));
    return make_float2(lo, hi);
}
__device__ __forceinline__ float lrelu(float v) {
    return (v > 0.f) ? v : v * NEG_SLOPE;
}

// ---------------- Kernel 0: zero degrees + detect dtype ----------------
__global__ void detect_zero_kernel(const int* __restrict__ ei32, int E, int n)
{
    int i = blockIdx.x * 256 + threadIdx.x;
    if (i < n) g_deg[i] = 0;
    if (blockIdx.x == 0) {
        int checks = 2 * E; if (checks > 4096) checks = 4096;
        int nz = 0;
        for (int j = threadIdx.x; j < checks; j += 256)
            if (ei32[2 * j + 1] != 0) nz = 1;
        #pragma unroll
        for (int o = 16; o >= 1; o >>= 1)
            nz |= __shfl_xor_sync(0xffffffffu, nz, o);
        __shared__ int s_nz[8];
        if ((threadIdx.x & 31) == 0) s_nz[threadIdx.x >> 5] = nz;
        __syncthreads();
        if (threadIdx.x == 0) {
            int a = 0;
            for (int w = 0; w < 8; w++) a |= s_nz[w];
            g_is64 = (a == 0) ? 1 : 0;
        }
    }
}

__device__ __forceinline__ int edge_src(const void* ei, int E, int e) {
    if (g_is64) return (int)((const long long*)ei)[e];
    return ((const int*)ei)[e];
}
__device__ __forceinline__ int edge_dst(const void* ei, int E, int e) {
    if (g_is64) return (int)((const long long*)ei)[E + e];
    return ((const int*)ei)[E + e];
}

// ---------------- Kernel 1: h = x @ W + logits (persistent, dbl-buffered)
__global__ __launch_bounds__(256, 2)
void gemm_kernel(const float* __restrict__ x, const float* __restrict__ W,
                 const float* __restrict__ att_src, const float* __restrict__ att_dst,
                 int n, int ntiles)
{
    extern __shared__ float smem[];
    float* ws = smem;                       // [128][128] = 64KB
    float* xa = smem + 128 * 128;           // [32][128] = 16KB
    float* xb = xa + TILE_R * 128;          // [32][128] = 16KB

    int tid = threadIdx.x;
    int rg = tid >> 5;
    int cg = tid & 31;

    const float4* W4 = (const float4*)W;
    float4* ws4 = (float4*)ws;
    #pragma unroll
    for (int t = tid; t < 4096; t += 256) ws4[t] = W4[t];

    float4 as4 = ((const float4*)att_src)[cg];
    float4 ad4 = ((const float4*)att_dst)[cg];
    float4* h4 = (float4*)g_h;
    const float4* x4in = (const float4*)x;
    const ulonglong2* ws2 = (const ulonglong2*)ws;
    int head = cg >> 3;

    int tile = blockIdx.x;
    float4 pf[4];
    {
        int rowbase = tile * TILE_R;
        #pragma unroll
        for (int j = 0; j < 4; j++) {
            int t = tid + j * 256;
            int r = t >> 5, k4 = t & 31;
            int grow = rowbase + r;
            pf[j] = (tile < ntiles && grow < n) ? x4in[grow * 32 + k4]
                                                : make_float4(0.f, 0.f, 0.f, 0.f);
        }
    }

    int cur = 0;
    for (; tile < ntiles; tile += gridDim.x) {
        float* xbuf = cur ? xb : xa;
        float4* xs4 = (float4*)xbuf;

        #pragma unroll
        for (int j = 0; j < 4; j++) xs4[tid + j * 256] = pf[j];
        __syncthreads();

        int ntile = tile + gridDim.x;
        {
            int rowbase = ntile * TILE_R;
            #pragma unroll
            for (int j = 0; j < 4; j++) {
                int t = tid + j * 256;
                int r = t >> 5, k4 = t & 31;
                int grow = rowbase + r;
                pf[j] = (ntile < ntiles && grow < n) ? x4in[grow * 32 + k4]
                                                     : make_float4(0.f, 0.f, 0.f, 0.f);
            }
        }

        unsigned long long acc0[4], acc1[4];
        #pragma unroll
        for (int i = 0; i < 4; i++) { acc0[i] = 0ull; acc1[i] = 0ull; }

        const float* xrow = xbuf + rg * 4 * 128;

        #pragma unroll 4
        for (int k4 = 0; k4 < 32; k4++) {
            ulonglong2 wv0 = ws2[(k4 * 4 + 0) * 32 + cg];
            ulonglong2 wv1 = ws2[(k4 * 4 + 1) * 32 + cg];
            ulonglong2 wv2 = ws2[(k4 * 4 + 2) * 32 + cg];
            ulonglong2 wv3 = ws2[(k4 * 4 + 3) * 32 + cg];
            #pragma unroll
            for (int i = 0; i < 4; i++) {
                float4 xv = *(const float4*)(xrow + i * 128 + k4 * 4);
                unsigned long long p0 = pk2(xv.x, xv.x);
                unsigned long long p1 = pk2(xv.y, xv.y);
                unsigned long long p2 = pk2(xv.z, xv.z);
                unsigned long long p3 = pk2(xv.w, xv.w);
                acc0[i] = fma2(p0, wv0.x, acc0[i]); acc1[i] = fma2(p0, wv0.y, acc1[i]);
                acc0[i] = fma2(p1, wv1.x, acc0[i]); acc1[i] = fma2(p1, wv1.y, acc1[i]);
                acc0[i] = fma2(p2, wv2.x, acc0[i]); acc1[i] = fma2(p2, wv2.y, acc1[i]);
                acc0[i] = fma2(p3, wv3.x, acc0[i]); acc1[i] = fma2(p3, wv3.y, acc1[i]);
            }
        }

        int rowbase = tile * TILE_R;
        #pragma unroll
        for (int i = 0; i < 4; i++) {
            float2 a = upk2(acc0[i]);
            float2 b = upk2(acc1[i]);
            float4 hv = make_float4(a.x, a.y, b.x, b.y);
            float ps = hv.x * as4.x + hv.y * as4.y + hv.z * as4.z + hv.w * as4.w;
            float pd = hv.x * ad4.x + hv.y * ad4.y + hv.z * ad4.z + hv.w * ad4.w;
            #pragma unroll
            for (int o = 4; o >= 1; o >>= 1) {
                ps += __shfl_xor_sync(0xffffffffu, ps, o);
                pd += __shfl_xor_sync(0xffffffffu, pd, o);
            }
            int grow = rowbase + rg * 4 + i;
            if (grow < n) {
                h4[grow * 32 + cg] = hv;
                if ((cg & 7) == 0) {
                    g_asrc[grow * HH + head] = ps;
                    g_adst[grow * HH + head] = pd;
                }
            }
        }

        cur ^= 1;
        __syncthreads();
    }
}

// ---------------- CSR build kernels (proven) ----------------------------
__global__ void hist_kernel(const void* __restrict__ ei, int E)
{
    int e = blockIdx.x * 256 + threadIdx.x;
    if (e < E) atomicAdd(&g_deg[edge_dst(ei, E, e)], 1);
}

__global__ __launch_bounds__(256)
void scan_local_kernel(int n)
{
    int i = blockIdx.x * 256 + threadIdx.x;
    int lane = threadIdx.x & 31;
    int wid  = threadIdx.x >> 5;
    int v = (i < n) ? g_deg[i] : 0;
    int inc = v;
    #pragma unroll
    for (int o = 1; o < 32; o <<= 1) {
        int t = __shfl_up_sync(0xffffffffu, inc, o);
        if (lane >= o) inc += t;
    }
    __shared__ int wsum[8];
    if (lane == 31) wsum[wid] = inc;
    __syncthreads();
    if (wid == 0) {
        int ws = (lane < 8) ? wsum[lane] : 0;
        #pragma unroll
        for (int o = 1; o < 8; o <<= 1) {
            int t = __shfl_up_sync(0xffffffffu, ws, o);
            if (lane >= o) ws += t;
        }
        if (lane < 8) wsum[lane] = ws;
    }
    __syncthreads();
    int warpbase = (wid == 0) ? 0 : wsum[wid - 1];
    int excl = warpbase + inc - v;
    if (i < n) g_rowoff[i] = excl;
    if (threadIdx.x == 255) g_bsum[blockIdx.x] = warpbase + inc;
}

__global__ __launch_bounds__(256)
void scan_fixup_kernel(int n, int nb)
{
    __shared__ int s_base;
    if (threadIdx.x < 32) {
        int b = 0;
        for (int j = threadIdx.x; j < blockIdx.x; j += 32) b += g_bsum[j];
        #pragma unroll
        for (int o = 16; o >= 1; o >>= 1)
            b += __shfl_xor_sync(0xffffffffu, b, o);
        if (threadIdx.x == 0) s_base = b;
    }
    __syncthreads();
    int i = blockIdx.x * 256 + threadIdx.x;
    if (i < n) {
        int r = g_rowoff[i] + s_base;
        g_rowoff[i] = r;
        g_cursor[i] = r;
    }
}

__global__ void scatter_kernel(const void* __restrict__ ei, int E)
{
    int e = blockIdx.x * 256 + threadIdx.x;
    if (e < E) {
        int s = edge_src(ei, E, e);
        int d = edge_dst(ei, E, e);
        int pos = atomicAdd(&g_cursor[d], 1);
        g_srclist[pos] = s;
    }
}

// ---------------- Kernel 5: fused softmax-agg + GELU + LN + residual ----
// No max subtraction (R16-proven). NEW: node's srclist fetched with ONE
// coalesced lane-parallel LDG; main loop gets sids via __shfl_sync instead
// of per-group scalar LDGs, removing the srclist link of the latency chain.
__global__ __launch_bounds__(256)
void agg_ln_kernel(const float* __restrict__ x,
                   const float* __restrict__ bias,
                   const float* __restrict__ gamma,
                   const float* __restrict__ beta,
                   float* __restrict__ out, int n)
{
    int node = blockIdx.x * 8 + (threadIdx.x >> 5);
    if (node >= n) return;
    int lane = threadIdx.x & 31;
    int hd8 = lane >> 3;

    int beg = g_rowoff[node];
    int cnt = g_deg[node];

    float adst   = g_adst[node * HH + hd8];
    float aselfh = g_asrc[node * HH + hd8];

    // lane-parallel srclist fetch (covers first min(cnt,32) edges)
    int m = (cnt < 32) ? cnt : 32;
    int lane_sid = (lane < m) ? g_srclist[beg + lane] : 0;

    const float4* h4 = (const float4*)g_h;
    float p0 = __expf(lrelu(aselfh + adst));
    float4 hv = h4[node * 32 + lane];
    float4 accA = make_float4(p0 * hv.x, p0 * hv.y, p0 * hv.z, p0 * hv.w);
    float4 accB = make_float4(0.f, 0.f, 0.f, 0.f);
    float4 accC = make_float4(0.f, 0.f, 0.f, 0.f);
    float4 accD = make_float4(0.f, 0.f, 0.f, 0.f);
    float dA = p0, dB = 0.f, dC = 0.f, dD = 0.f;

    int k = 0;
    for (; k + 4 <= m; k += 4) {
        int sa = __shfl_sync(0xffffffffu, lane_sid, k);
        int sb = __shfl_sync(0xffffffffu, lane_sid, k + 1);
        int sc = __shfl_sync(0xffffffffu, lane_sid, k + 2);
        int sd = __shfl_sync(0xffffffffu, lane_sid, k + 3);
        float ea = g_asrc[sa * HH + hd8];
        float eb = g_asrc[sb * HH + hd8];
        float ec = g_asrc[sc * HH + hd8];
        float ed = g_asrc[sd * HH + hd8];
        float4 ha = h4[sa * 32 + lane];
        float4 hb = h4[sb * 32 + lane];
        float4 hc = h4[sc * 32 + lane];
        float4 hd = h4[sd * 32 + lane];
        float pa = __expf(lrelu(ea + adst));
        float pb = __expf(lrelu(eb + adst));
        float pc = __expf(lrelu(ec + adst));
        float pd = __expf(lrelu(ed + adst));
        dA += pa; dB += pb; dC += pc; dD += pd;
        accA.x = fmaf(pa, ha.x, accA.x); accA.y = fmaf(pa, ha.y, accA.y);
        accA.z = fmaf(pa, ha.z, accA.z); accA.w = fmaf(pa, ha.w, accA.w);
        accB.x = fmaf(pb, hb.x, accB.x); accB.y = fmaf(pb, hb.y, accB.y);
        accB.z = fmaf(pb, hb.z, accB.z); accB.w = fmaf(pb, hb.w, accB.w);
        accC.x = fmaf(pc, hc.x, accC.x); accC.y = fmaf(pc, hc.y, accC.y);
        accC.z = fmaf(pc, hc.z, accC.z); accC.w = fmaf(pc, hc.w, accC.w);
        accD.x = fmaf(pd, hd.x, accD.x); accD.y = fmaf(pd, hd.y, accD.y);
        accD.z = fmaf(pd, hd.z, accD.z); accD.w = fmaf(pd, hd.w, accD.w);
    }
    for (; k < m; k++) {
        int sa = __shfl_sync(0xffffffffu, lane_sid, k);
        float ea = g_asrc[sa * HH + hd8];
        float4 ha = h4[sa * 32 + lane];
        float pa = __expf(lrelu(ea + adst));
        dA += pa;
        accA.x = fmaf(pa, ha.x, accA.x); accA.y = fmaf(pa, ha.y, accA.y);
        accA.z = fmaf(pa, ha.z, accA.z); accA.w = fmaf(pa, ha.w, accA.w);
    }
    // rare tail: cnt > 32 — original gather path
    for (; k < cnt; k++) {
        int sa = g_srclist[beg + k];
        float ea = g_asrc[sa * HH + hd8];
        float4 ha = h4[sa * 32 + lane];
        float pa = __expf(lrelu(ea + adst));
        dA += pa;
        accA.x = fmaf(pa, ha.x, accA.x); accA.y = fmaf(pa, ha.y, accA.y);
        accA.z = fmaf(pa, ha.z, accA.z); accA.w = fmaf(pa, ha.w, accA.w);
    }

    float denom = (dA + dB) + (dC + dD);
    float inv = 1.0f / denom;
    float4 bi = ((const float4*)bias)[lane];
    float4 sum = make_float4((accA.x + accB.x) + (accC.x + accD.x),
                             (accA.y + accB.y) + (accC.y + accD.y),
                             (accA.z + accB.z) + (accC.z + accD.z),
                             (accA.w + accB.w) + (accC.w + accD.w));
    float4 o = make_float4(fmaf(sum.x, inv, bi.x), fmaf(sum.y, inv, bi.y),
                           fmaf(sum.z, inv, bi.z), fmaf(sum.w, inv, bi.w));

    const float RS2 = 0.70710678118654752f;
    float4 f;
    f.x = 0.5f * o.x * (1.0f + erff(o.x * RS2));
    f.y = 0.5f * o.y * (1.0f + erff(o.y * RS2));
    f.z = 0.5f * o.z * (1.0f + erff(o.z * RS2));
    f.w = 0.5f * o.w * (1.0f + erff(o.w * RS2));

    float s1 = f.x + f.y + f.z + f.w;
    float s2 = f.x * f.x + f.y * f.y + f.z * f.z + f.w * f.w;
    #pragma unroll
    for (int off = 16; off >= 1; off >>= 1) {
        s1 += __shfl_xor_sync(0xffffffffu, s1, off);
        s2 += __shfl_xor_sync(0xffffffffu, s2, off);
    }
    float mu  = s1 * (1.0f / 128.0f);
    float var = s2 * (1.0f / 128.0f) - mu * mu;
    float r = rsqrtf(var + LN_EPS);

    float4 gm = ((const float4*)gamma)[lane];
    float4 bt = ((const float4*)beta)[lane];
    float4 xv = ((const float4*)x)[node * 32 + lane];
    float4 res;
    res.x = (f.x - mu) * r * gm.x + bt.x + xv.x;
    res.y = (f.y - mu) * r * gm.y + bt.y + xv.y;
    res.z = (f.z - mu) * r * gm.z + bt.z + xv.z;
    res.w = (f.w - mu) * r * gm.w + bt.w + xv.w;
    ((float4*)out)[node * 32 + lane] = res;
}

// ---------------- launch: gemm(+logits) || CSR-build, join at agg -------
extern "C" void kernel_launch(void* const* d_in, const int* in_sizes, int n_in,
                              void* d_out, int out_size)
{
    const float* x       = (const float*)d_in[0];
    const void*  ei      = d_in[1];
    const float* W       = (const float*)d_in[2];
    const float* att_src = (const float*)d_in[3];
    const float* att_dst = (const float*)d_in[4];
    const float* bias    = (const float*)d_in[5];
    const float* gamma   = (const float*)d_in[6];
    const float* beta    = (const float*)d_in[7];
    float*       out     = (float*)d_out;

    int n = in_sizes[0] / DD;     // 50000
    int E = in_sizes[1] / 2;      // 600000
    int nb = (n + 255) / 256;     // 196
    int ntiles = (n + TILE_R - 1) / TILE_R;   // 1563

    const int GEMM_SMEM = (128 * 128 + 2 * TILE_R * 128) * 4;  // 96KB
    static bool s_init = false;
    static cudaStream_t s2;
    static cudaEvent_t evFork, evJoin;
    static int s_sms = 148;
    if (!s_init) {
        cudaFuncSetAttribute(gemm_kernel,
                             cudaFuncAttributeMaxDynamicSharedMemorySize, GEMM_SMEM);
        cudaStreamCreateWithFlags(&s2, cudaStreamNonBlocking);
        cudaEventCreateWithFlags(&evFork, cudaEventDisableTiming);
        cudaEventCreateWithFlags(&evJoin, cudaEventDisableTiming);
        int dev = 0; cudaGetDevice(&dev);
        cudaDeviceGetAttribute(&s_sms, cudaDevAttrMultiProcessorCount, dev);
        s_init = true;
    }

    int gemm_grid = 2 * s_sms;
    if (gemm_grid > ntiles) gemm_grid = ntiles;

    cudaEventRecord(evFork, 0);
    cudaStreamWaitEvent(s2, evFork, 0);

    gemm_kernel<<<gemm_grid, 256, GEMM_SMEM>>>(x, W, att_src, att_dst, n, ntiles);

    detect_zero_kernel<<<nb, 256, 0, s2>>>((const int*)ei, E, n);
    hist_kernel<<<(E + 255) / 256, 256, 0, s2>>>(ei, E);
    scan_local_kernel<<<nb, 256, 0, s2>>>(n);
    scan_fixup_kernel<<<nb, 256, 0, s2>>>(n, nb);
    scatter_kernel<<<(E + 255) / 256, 256, 0, s2>>>(ei, E);

    cudaEventRecord(evJoin, s2);
    cudaStreamWaitEvent(0, evJoin, 0);

    agg_ln_kernel<<<(n + 7) / 8, 256>>>(x, bias, gamma, beta, out, n);
}